// round 1
// baseline (speedup 1.0000x reference)
#include <cuda_runtime.h>
#include <math.h>

#define SEQ   4096
#define HID   2048
#define NHEADS 16
#define HD    128
#define QKVN  6144   // (16 + 2*16) * 128

// Scratch (no cudaMalloc allowed)
__device__ float g_qkv[SEQ * QKVN];   // ~100.7 MB
__device__ float g_attn[SEQ * HID];   // ~33.6 MB

// ---------------------------------------------------------------------------
// SGEMM NT: C[M,N] = A[M,K] * B[N,K]^T   (both operands K-major, fp32)
// 128x128 tile, BK=8, 256 threads, 8x8 micro-tile per thread.
// ---------------------------------------------------------------------------
__global__ void __launch_bounds__(256) sgemm_nt_kernel(
    const float* __restrict__ A, const float* __restrict__ B,
    float* __restrict__ C, int M, int N, int K)
{
    __shared__ float As[8][132];
    __shared__ float Bs[8][132];

    int tid = threadIdx.x;
    int tx = tid & 15;        // col group (8 cols)
    int ty = tid >> 4;        // row group (8 rows)
    int m0 = blockIdx.y * 128;
    int n0 = blockIdx.x * 128;

    int lrow = tid >> 1;          // 0..127
    int lc   = (tid & 1) * 4;     // 0 or 4
    const float* Ap = A + (size_t)(m0 + lrow) * K + lc;
    const float* Bp = B + (size_t)(n0 + lrow) * K + lc;

    float acc[8][8];
    #pragma unroll
    for (int i = 0; i < 8; i++)
        #pragma unroll
        for (int j = 0; j < 8; j++) acc[i][j] = 0.f;

    for (int k0 = 0; k0 < K; k0 += 8) {
        float4 a4 = *(const float4*)(Ap + k0);
        float4 b4 = *(const float4*)(Bp + k0);
        __syncthreads();
        As[lc + 0][lrow] = a4.x; As[lc + 1][lrow] = a4.y;
        As[lc + 2][lrow] = a4.z; As[lc + 3][lrow] = a4.w;
        Bs[lc + 0][lrow] = b4.x; Bs[lc + 1][lrow] = b4.y;
        Bs[lc + 2][lrow] = b4.z; Bs[lc + 3][lrow] = b4.w;
        __syncthreads();

        #pragma unroll
        for (int kk = 0; kk < 8; kk++) {
            float ra[8], rb[8];
            *(float4*)&ra[0] = *(const float4*)&As[kk][ty * 8];
            *(float4*)&ra[4] = *(const float4*)&As[kk][ty * 8 + 4];
            *(float4*)&rb[0] = *(const float4*)&Bs[kk][tx * 8];
            *(float4*)&rb[4] = *(const float4*)&Bs[kk][tx * 8 + 4];
            #pragma unroll
            for (int i = 0; i < 8; i++)
                #pragma unroll
                for (int j = 0; j < 8; j++)
                    acc[i][j] = fmaf(ra[i], rb[j], acc[i][j]);
        }
    }

    #pragma unroll
    for (int i = 0; i < 8; i++) {
        float* Crow = C + (size_t)(m0 + ty * 8 + i) * N + n0 + tx * 8;
        *(float4*)(Crow)     = make_float4(acc[i][0], acc[i][1], acc[i][2], acc[i][3]);
        *(float4*)(Crow + 4) = make_float4(acc[i][4], acc[i][5], acc[i][6], acc[i][7]);
    }
}

// ---------------------------------------------------------------------------
// RoPE applied in-place to q (heads 0..15) and k (heads 16..31) of g_qkv.
// Matches jax fp32: freqs = s * (1 / 10000^(2i/128)), pair (i, i+64).
// ---------------------------------------------------------------------------
__global__ void __launch_bounds__(256) rope_kernel()
{
    int s = blockIdx.x;
    __shared__ float cs[64], sn[64];
    int t = threadIdx.x;
    if (t < 64) {
        float ex  = (float)(2 * t) / 128.0f;
        float inv = 1.0f / powf(10000.0f, ex);
        float f   = (float)s * inv;
        cs[t] = cosf(f);
        sn[t] = sinf(f);
    }
    __syncthreads();
    float* base = g_qkv + (size_t)s * QKVN;
    for (int p = t; p < 2 * NHEADS * 64; p += 256) {
        int h = p >> 6;
        int i = p & 63;
        float* x = base + h * HD;
        float xr = x[i], xi = x[i + 64];
        float c = cs[i], ss = sn[i];
        x[i]      = xr * c - xi * ss;
        x[i + 64] = xi * c + xr * ss;
    }
}

// ---------------------------------------------------------------------------
// Flash attention, fp32, causal. One CTA = (64 queries) x (1 head).
// Q stored k-major (transposed) in smem for conflict-free score loads.
// Thread map: tx (0..15) -> 4 query rows, ty (0..15) -> 4 score cols / 8 O cols.
// ---------------------------------------------------------------------------
__global__ void __launch_bounds__(256) flash_kernel()
{
    extern __shared__ float sm[];
    float* Qt  = sm;                   // [128][64]  k-major
    float* Ks  = Qt + 128 * 64;        // [64][128]
    float* Vs  = Ks + 64 * 128;        // [64][128]
    float* Ss  = Vs + 64 * 128;        // [64][65]   padded
    float* m_s = Ss + 64 * 65;         // [64]
    float* l_s = m_s + 64;             // [64]
    float* f_s = l_s + 64;             // [64] rescale factors

    int head = blockIdx.y;
    int q0   = blockIdx.x * 64;
    int tid  = threadIdx.x;
    int tx   = tid & 15;
    int ty   = tid >> 4;

    // Load + transpose Q tile (once per CTA)
    const float* Qg = g_qkv + (size_t)q0 * QKVN + head * HD;
    for (int idx = tid; idx < 64 * 32; idx += 256) {
        int r = idx >> 5;
        int c = (idx & 31) << 2;
        float4 v = *(const float4*)(Qg + (size_t)r * QKVN + c);
        Qt[(c + 0) * 64 + r] = v.x;
        Qt[(c + 1) * 64 + r] = v.y;
        Qt[(c + 2) * 64 + r] = v.z;
        Qt[(c + 3) * 64 + r] = v.w;
    }
    if (tid < 64) { m_s[tid] = -1e30f; l_s[tid] = 0.f; }

    float acc[4][8];
    #pragma unroll
    for (int i = 0; i < 4; i++)
        #pragma unroll
        for (int j = 0; j < 8; j++) acc[i][j] = 0.f;

    const float scale = 0.08838834764831845f;  // 1/sqrt(128)
    const float* Kg = g_qkv + (size_t)(NHEADS + head) * HD;
    const float* Vg = g_qkv + (size_t)(2 * NHEADS + head) * HD;

    int ntiles = (q0 >> 6) + 1;
    for (int kt = 0; kt < ntiles; kt++) {
        int k0 = kt << 6;
        __syncthreads();  // protect previous-iter smem reads
        for (int idx = tid; idx < 64 * 32; idx += 256) {
            int r = idx >> 5;
            int c = (idx & 31) << 2;
            *(float4*)(Ks + r * HD + c) = *(const float4*)(Kg + (size_t)(k0 + r) * QKVN + c);
            *(float4*)(Vs + r * HD + c) = *(const float4*)(Vg + (size_t)(k0 + r) * QKVN + c);
        }
        __syncthreads();

        // Scores: 4x4 per thread, rows = tx*4+i, cols = ty*4+j
        float sc[4][4];
        #pragma unroll
        for (int i = 0; i < 4; i++)
            #pragma unroll
            for (int j = 0; j < 4; j++) sc[i][j] = 0.f;

        #pragma unroll 8
        for (int k = 0; k < HD; k += 4) {
            float qv[4][4];   // [kk][i]
            #pragma unroll
            for (int kk = 0; kk < 4; kk++)
                *(float4*)qv[kk] = *(const float4*)(Qt + (k + kk) * 64 + tx * 4);
            float kv[4][4];   // [j][kk]
            #pragma unroll
            for (int j = 0; j < 4; j++)
                *(float4*)kv[j] = *(const float4*)(Ks + (ty * 4 + j) * HD + k);
            #pragma unroll
            for (int kk = 0; kk < 4; kk++)
                #pragma unroll
                for (int i = 0; i < 4; i++)
                    #pragma unroll
                    for (int j = 0; j < 4; j++)
                        sc[i][j] = fmaf(qv[kk][i], kv[j][kk], sc[i][j]);
        }

        bool diag = (k0 == q0);
        #pragma unroll
        for (int i = 0; i < 4; i++)
            #pragma unroll
            for (int j = 0; j < 4; j++) {
                float v = sc[i][j] * scale;
                if (diag && (k0 + ty * 4 + j) > (q0 + tx * 4 + i)) v = -1e30f;
                Ss[(tx * 4 + i) * 65 + ty * 4 + j] = v;
            }
        __syncthreads();

        // Online softmax: 4 threads per row
        {
            int r = tid >> 2, sub = tid & 3;
            float mx = -1e30f;
            #pragma unroll
            for (int cc = 0; cc < 16; cc++)
                mx = fmaxf(mx, Ss[r * 65 + sub + (cc << 2)]);
            mx = fmaxf(mx, __shfl_xor_sync(0xffffffffu, mx, 1));
            mx = fmaxf(mx, __shfl_xor_sync(0xffffffffu, mx, 2));
            float mold = m_s[r];
            float mnew = fmaxf(mold, mx);
            float sum = 0.f;
            #pragma unroll
            for (int cc = 0; cc < 16; cc++) {
                int ix = r * 65 + sub + (cc << 2);
                float p = __expf(Ss[ix] - mnew);
                Ss[ix] = p;
                sum += p;
            }
            sum += __shfl_xor_sync(0xffffffffu, sum, 1);
            sum += __shfl_xor_sync(0xffffffffu, sum, 2);
            if (sub == 0) {
                float f = __expf(mold - mnew);
                m_s[r] = mnew;
                l_s[r] = l_s[r] * f + sum;
                f_s[r] = f;
            }
        }
        __syncthreads();

        // Rescale accumulators, then P*V: rows tx*4+i, cols ty*8+j
        float rs[4];
        #pragma unroll
        for (int i = 0; i < 4; i++) rs[i] = f_s[tx * 4 + i];
        #pragma unroll
        for (int i = 0; i < 4; i++)
            #pragma unroll
            for (int j = 0; j < 8; j++) acc[i][j] *= rs[i];

        #pragma unroll 4
        for (int k = 0; k < 64; k++) {
            float p[4];
            #pragma unroll
            for (int i = 0; i < 4; i++) p[i] = Ss[(tx * 4 + i) * 65 + k];
            float v[8];
            *(float4*)&v[0] = *(const float4*)(Vs + k * HD + ty * 8);
            *(float4*)&v[4] = *(const float4*)(Vs + k * HD + ty * 8 + 4);
            #pragma unroll
            for (int i = 0; i < 4; i++)
                #pragma unroll
                for (int j = 0; j < 8; j++)
                    acc[i][j] = fmaf(p[i], v[j], acc[i][j]);
        }
    }

    // Normalize + store (l_s finalized before last PV's preceding sync)
    #pragma unroll
    for (int i = 0; i < 4; i++) {
        float inv = 1.0f / l_s[tx * 4 + i];
        float* orow = g_attn + (size_t)(q0 + tx * 4 + i) * HID + head * HD + ty * 8;
        *(float4*)(orow)     = make_float4(acc[i][0] * inv, acc[i][1] * inv,
                                           acc[i][2] * inv, acc[i][3] * inv);
        *(float4*)(orow + 4) = make_float4(acc[i][4] * inv, acc[i][5] * inv,
                                           acc[i][6] * inv, acc[i][7] * inv);
    }
}

// ---------------------------------------------------------------------------
extern "C" void kernel_launch(void* const* d_in, const int* in_sizes, int n_in,
                              void* d_out, int out_size)
{
    const float* hidden = (const float*)d_in[0];   // [4096, 2048]
    const float* w_qkv  = (const float*)d_in[1];   // [6144, 2048]
    const float* w_o    = (const float*)d_in[2];   // [2048, 2048]
    float* out = (float*)d_out;                    // [4096, 2048]

    float *qkv_ptr, *attn_ptr;
    cudaGetSymbolAddress((void**)&qkv_ptr, g_qkv);
    cudaGetSymbolAddress((void**)&attn_ptr, g_attn);

    // 1) QKV projection
    dim3 g1(QKVN / 128, SEQ / 128);
    sgemm_nt_kernel<<<g1, 256>>>(hidden, w_qkv, qkv_ptr, SEQ, QKVN, HID);

    // 2) RoPE on q and k
    rope_kernel<<<SEQ, 256>>>();

    // 3) Causal flash attention
    size_t smem = (size_t)(128 * 64 + 64 * 128 * 2 + 64 * 65 + 3 * 64) * sizeof(float);
    cudaFuncSetAttribute(flash_kernel, cudaFuncAttributeMaxDynamicSharedMemorySize,
                         (int)smem);
    flash_kernel<<<dim3(SEQ / 64, NHEADS), 256, smem>>>();

    // 4) Output projection
    dim3 g2(HID / 128, SEQ / 128);
    sgemm_nt_kernel<<<g2, 256>>>(attn_ptr, w_o, out, SEQ, HID, HID);
}

// round 3
// speedup vs baseline: 1.6871x; 1.6871x over previous
#include <cuda_runtime.h>
#include <cuda_bf16.h>
#include <math.h>
#include <cstdint>

#define SEQ   4096
#define HID   2048
#define NHEADS 16
#define HD    128
#define QKVN  6144   // (16 + 2*16) * 128

// Scratch (no cudaMalloc allowed)
__device__ float g_qkv[SEQ * QKVN];    // fp32 qkv after projection
__device__ float g_attn[SEQ * HID];    // fp32 attention output

// bf16 hi/lo planes for HMMA GEMMs
__device__ __nv_bfloat16 g_hid_h[SEQ * HID];
__device__ __nv_bfloat16 g_hid_l[SEQ * HID];
__device__ __nv_bfloat16 g_wq_h[QKVN * HID];
__device__ __nv_bfloat16 g_wq_l[QKVN * HID];
__device__ __nv_bfloat16 g_wo_h[HID * HID];
__device__ __nv_bfloat16 g_wo_l[HID * HID];
__device__ __nv_bfloat16 g_at_h[SEQ * HID];
__device__ __nv_bfloat16 g_at_l[SEQ * HID];

// ---------------------------------------------------------------------------
__device__ __forceinline__ uint32_t smem_u32(const void* p) {
    uint32_t a;
    asm("{ .reg .u64 t; cvta.to.shared.u64 t, %1; cvt.u32.u64 %0, t; }"
        : "=r"(a) : "l"(p));
    return a;
}

__device__ __forceinline__ void ldsm4(uint32_t* r, uint32_t addr) {
    asm volatile("ldmatrix.sync.aligned.m8n8.x4.shared.b16 {%0,%1,%2,%3}, [%4];"
                 : "=r"(r[0]), "=r"(r[1]), "=r"(r[2]), "=r"(r[3]) : "r"(addr));
}

__device__ __forceinline__ void mma16816(float* c, const uint32_t* a, const uint32_t* b) {
    asm volatile(
        "mma.sync.aligned.m16n8k16.row.col.f32.bf16.bf16.f32 "
        "{%0,%1,%2,%3}, {%4,%5,%6,%7}, {%8,%9}, {%0,%1,%2,%3};"
        : "+f"(c[0]), "+f"(c[1]), "+f"(c[2]), "+f"(c[3])
        : "r"(a[0]), "r"(a[1]), "r"(a[2]), "r"(a[3]), "r"(b[0]), "r"(b[1]));
}

// ---------------------------------------------------------------------------
// Split fp32 -> bf16 hi + bf16 lo (lo = bf16(x - float(hi)))
// ---------------------------------------------------------------------------
__global__ void __launch_bounds__(256) split_kernel(
    const float* __restrict__ in, __nv_bfloat16* __restrict__ hi,
    __nv_bfloat16* __restrict__ lo, int n4)
{
    int i = blockIdx.x * 256 + threadIdx.x;
    if (i >= n4) return;
    float4 v = ((const float4*)in)[i];
    __nv_bfloat162 h0 = __float22bfloat162_rn(make_float2(v.x, v.y));
    __nv_bfloat162 h1 = __float22bfloat162_rn(make_float2(v.z, v.w));
    float2 g0 = __bfloat1622float2(h0);
    float2 g1 = __bfloat1622float2(h1);
    __nv_bfloat162 l0 = __float22bfloat162_rn(make_float2(v.x - g0.x, v.y - g0.y));
    __nv_bfloat162 l1 = __float22bfloat162_rn(make_float2(v.z - g1.x, v.w - g1.y));
    ((uint2*)hi)[i] = make_uint2(*(uint32_t*)&h0, *(uint32_t*)&h1);
    ((uint2*)lo)[i] = make_uint2(*(uint32_t*)&l0, *(uint32_t*)&l1);
}

// ---------------------------------------------------------------------------
// bf16x3 HMMA GEMM NT: C[M,N] = A[M,K] * B[N,K]^T, fp32 accumulate.
// CTA 128x128, BK=32, 256 threads (8 warps, 4x2), warp tile 32x64.
// Smem: 80B row pitch (32 bf16 + 16B pad) -> conflict-free ldmatrix.
// Double-buffered cp.async.
// ---------------------------------------------------------------------------
#define GPITCH 80          // bytes per smem row (32 bf16 = 64B data + 16B pad)
#define PLANE  (128 * GPITCH)   // 10240 bytes per plane
#define STAGE  (4 * PLANE)      // 40960 bytes per stage (Ah, Al, Bh, Bl)

__global__ void __launch_bounds__(256, 2)
gemm_bf16x3(const __nv_bfloat16* __restrict__ Ah, const __nv_bfloat16* __restrict__ Al,
            const __nv_bfloat16* __restrict__ Bh, const __nv_bfloat16* __restrict__ Bl,
            float* __restrict__ C, int M, int N, int K)
{
    extern __shared__ char smc[];
    uint32_t sbase = smem_u32(smc);

    const int tid  = threadIdx.x;
    const int lane = tid & 31;
    const int wid  = tid >> 5;
    const int m0 = blockIdx.y * 128;
    const int n0 = blockIdx.x * 128;
    const int wm = (wid & 3) * 32;
    const int wn = (wid >> 2) * 64;

    const __nv_bfloat16* gsrc0 = Ah + (size_t)m0 * K;
    const __nv_bfloat16* gsrc1 = Al + (size_t)m0 * K;
    const __nv_bfloat16* gsrc2 = Bh + (size_t)n0 * K;
    const __nv_bfloat16* gsrc3 = Bl + (size_t)n0 * K;

    const int lrow = tid >> 2;       // 0..63 (first 64 rows), +64 second pass
    const int lkg  = tid & 3;        // 16B chunk within row

    auto load_stage = [&](int s, int k0) {
        const __nv_bfloat16* gs[4] = {gsrc0 + k0, gsrc1 + k0, gsrc2 + k0, gsrc3 + k0};
        #pragma unroll
        for (int p = 0; p < 4; p++) {
            uint32_t sp = sbase + s * STAGE + p * PLANE;
            #pragma unroll
            for (int half = 0; half < 2; half++) {
                int row = lrow + half * 64;
                uint32_t sa = sp + row * GPITCH + lkg * 16;
                const void* ga = gs[p] + (size_t)row * K + lkg * 8;
                asm volatile("cp.async.cg.shared.global [%0], [%1], 16;"
                             :: "r"(sa), "l"(ga));
            }
        }
        asm volatile("cp.async.commit_group;");
    };

    float acc[2][8][4];
    #pragma unroll
    for (int a = 0; a < 2; a++)
        #pragma unroll
        for (int b = 0; b < 8; b++)
            #pragma unroll
            for (int c = 0; c < 4; c++) acc[a][b][c] = 0.f;

    const int nk = K >> 5;
    load_stage(0, 0);

    const int grp = lane >> 3, r8 = lane & 7;
    const int arow_off = r8 + ((grp & 1) << 3);   // A: matrices 0/1 rows, 2/3 k+8
    const int akk_off  = (grp >> 1) << 3;
    const int brow_off = r8 + ((grp >> 1) << 3);  // B: matrices 0/1 k halves, 2/3 rows+8
    const int bkk_off  = (grp & 1) << 3;

    for (int kt = 0; kt < nk; kt++) {
        int cur = kt & 1;
        if (kt + 1 < nk) {
            load_stage(cur ^ 1, (kt + 1) << 5);
            asm volatile("cp.async.wait_group 1;");
        } else {
            asm volatile("cp.async.wait_group 0;");
        }
        __syncthreads();

        uint32_t stg = sbase + cur * STAGE;
        uint32_t sAh = stg, sAl = stg + PLANE, sBh = stg + 2 * PLANE, sBl = stg + 3 * PLANE;

        #pragma unroll
        for (int ks = 0; ks < 2; ks++) {
            int kb = ks * 16;
            uint32_t a_h[2][4], a_l[2][4];
            #pragma unroll
            for (int mt = 0; mt < 2; mt++) {
                uint32_t ad = (uint32_t)((wm + mt * 16 + arow_off) * GPITCH
                                         + (kb + akk_off) * 2);
                ldsm4(a_h[mt], sAh + ad);
                ldsm4(a_l[mt], sAl + ad);
            }
            #pragma unroll
            for (int np = 0; np < 4; np++) {
                uint32_t bh[4], bl[4];
                uint32_t bd = (uint32_t)((wn + np * 16 + brow_off) * GPITCH
                                         + (kb + bkk_off) * 2);
                ldsm4(bh, sBh + bd);
                ldsm4(bl, sBl + bd);
                #pragma unroll
                for (int mt = 0; mt < 2; mt++) {
                    mma16816(acc[mt][np * 2],     a_h[mt], &bh[0]);
                    mma16816(acc[mt][np * 2],     a_h[mt], &bl[0]);
                    mma16816(acc[mt][np * 2],     a_l[mt], &bh[0]);
                    mma16816(acc[mt][np * 2 + 1], a_h[mt], &bh[2]);
                    mma16816(acc[mt][np * 2 + 1], a_h[mt], &bl[2]);
                    mma16816(acc[mt][np * 2 + 1], a_l[mt], &bh[2]);
                }
            }
        }
        __syncthreads();
    }

    // Epilogue: direct fp32 stores
    #pragma unroll
    for (int mt = 0; mt < 2; mt++) {
        int row0 = m0 + wm + mt * 16 + (lane >> 2);
        #pragma unroll
        for (int nt = 0; nt < 8; nt++) {
            int col = n0 + wn + nt * 8 + (lane & 3) * 2;
            *(float2*)(C + (size_t)row0 * N + col) =
                make_float2(acc[mt][nt][0], acc[mt][nt][1]);
            *(float2*)(C + (size_t)(row0 + 8) * N + col) =
                make_float2(acc[mt][nt][2], acc[mt][nt][3]);
        }
    }
}

// ---------------------------------------------------------------------------
// RoPE applied in-place to q (heads 0..15) and k (heads 16..31) of g_qkv.
// ---------------------------------------------------------------------------
__global__ void __launch_bounds__(256) rope_kernel()
{
    int s = blockIdx.x;
    __shared__ float cs[64], sn[64];
    int t = threadIdx.x;
    if (t < 64) {
        float ex  = (float)(2 * t) / 128.0f;
        float inv = 1.0f / powf(10000.0f, ex);
        float f   = (float)s * inv;
        cs[t] = cosf(f);
        sn[t] = sinf(f);
    }
    __syncthreads();
    float* base = g_qkv + (size_t)s * QKVN;
    for (int p = t; p < 2 * NHEADS * 64; p += 256) {
        int h = p >> 6;
        int i = p & 63;
        float* x = base + h * HD;
        float xr = x[i], xi = x[i + 64];
        float c = cs[i], ss = sn[i];
        x[i]      = xr * c - xi * ss;
        x[i + 64] = xi * c + xr * ss;
    }
}

// ---------------------------------------------------------------------------
// Flash attention, fp32, causal. One CTA = (64 queries) x (1 head).
// ---------------------------------------------------------------------------
__global__ void __launch_bounds__(256) flash_kernel()
{
    extern __shared__ float sm[];
    float* Qt  = sm;                   // [128][64]  k-major
    float* Ks  = Qt + 128 * 64;        // [64][128]
    float* Vs  = Ks + 64 * 128;        // [64][128]
    float* Ss  = Vs + 64 * 128;        // [64][65]
    float* m_s = Ss + 64 * 65;
    float* l_s = m_s + 64;
    float* f_s = l_s + 64;

    int head = blockIdx.y;
    int q0   = blockIdx.x * 64;
    int tid  = threadIdx.x;
    int tx   = tid & 15;
    int ty   = tid >> 4;

    const float* Qg = g_qkv + (size_t)q0 * QKVN + head * HD;
    for (int idx = tid; idx < 64 * 32; idx += 256) {
        int r = idx >> 5;
        int c = (idx & 31) << 2;
        float4 v = *(const float4*)(Qg + (size_t)r * QKVN + c);
        Qt[(c + 0) * 64 + r] = v.x;
        Qt[(c + 1) * 64 + r] = v.y;
        Qt[(c + 2) * 64 + r] = v.z;
        Qt[(c + 3) * 64 + r] = v.w;
    }
    if (tid < 64) { m_s[tid] = -1e30f; l_s[tid] = 0.f; }

    float acc[4][8];
    #pragma unroll
    for (int i = 0; i < 4; i++)
        #pragma unroll
        for (int j = 0; j < 8; j++) acc[i][j] = 0.f;

    const float scale = 0.08838834764831845f;
    const float* Kg = g_qkv + (size_t)(NHEADS + head) * HD;
    const float* Vg = g_qkv + (size_t)(2 * NHEADS + head) * HD;

    int ntiles = (q0 >> 6) + 1;
    for (int kt = 0; kt < ntiles; kt++) {
        int k0 = kt << 6;
        __syncthreads();
        for (int idx = tid; idx < 64 * 32; idx += 256) {
            int r = idx >> 5;
            int c = (idx & 31) << 2;
            *(float4*)(Ks + r * HD + c) = *(const float4*)(Kg + (size_t)(k0 + r) * QKVN + c);
            *(float4*)(Vs + r * HD + c) = *(const float4*)(Vg + (size_t)(k0 + r) * QKVN + c);
        }
        __syncthreads();

        float sc[4][4];
        #pragma unroll
        for (int i = 0; i < 4; i++)
            #pragma unroll
            for (int j = 0; j < 4; j++) sc[i][j] = 0.f;

        #pragma unroll 8
        for (int k = 0; k < HD; k += 4) {
            float qv[4][4];
            #pragma unroll
            for (int kk = 0; kk < 4; kk++)
                *(float4*)qv[kk] = *(const float4*)(Qt + (k + kk) * 64 + tx * 4);
            float kv[4][4];
            #pragma unroll
            for (int j = 0; j < 4; j++)
                *(float4*)kv[j] = *(const float4*)(Ks + (ty * 4 + j) * HD + k);
            #pragma unroll
            for (int kk = 0; kk < 4; kk++)
                #pragma unroll
                for (int i = 0; i < 4; i++)
                    #pragma unroll
                    for (int j = 0; j < 4; j++)
                        sc[i][j] = fmaf(qv[kk][i], kv[j][kk], sc[i][j]);
        }

        bool diag = (k0 == q0);
        #pragma unroll
        for (int i = 0; i < 4; i++)
            #pragma unroll
            for (int j = 0; j < 4; j++) {
                float v = sc[i][j] * scale;
                if (diag && (k0 + ty * 4 + j) > (q0 + tx * 4 + i)) v = -1e30f;
                Ss[(tx * 4 + i) * 65 + ty * 4 + j] = v;
            }
        __syncthreads();

        {
            int r = tid >> 2, sub = tid & 3;
            float mx = -1e30f;
            #pragma unroll
            for (int cc = 0; cc < 16; cc++)
                mx = fmaxf(mx, Ss[r * 65 + sub + (cc << 2)]);
            mx = fmaxf(mx, __shfl_xor_sync(0xffffffffu, mx, 1));
            mx = fmaxf(mx, __shfl_xor_sync(0xffffffffu, mx, 2));
            float mold = m_s[r];
            float mnew = fmaxf(mold, mx);
            float sum = 0.f;
            #pragma unroll
            for (int cc = 0; cc < 16; cc++) {
                int ix = r * 65 + sub + (cc << 2);
                float p = __expf(Ss[ix] - mnew);
                Ss[ix] = p;
                sum += p;
            }
            sum += __shfl_xor_sync(0xffffffffu, sum, 1);
            sum += __shfl_xor_sync(0xffffffffu, sum, 2);
            if (sub == 0) {
                float f = __expf(mold - mnew);
                m_s[r] = mnew;
                l_s[r] = l_s[r] * f + sum;
                f_s[r] = f;
            }
        }
        __syncthreads();

        float rs[4];
        #pragma unroll
        for (int i = 0; i < 4; i++) rs[i] = f_s[tx * 4 + i];
        #pragma unroll
        for (int i = 0; i < 4; i++)
            #pragma unroll
            for (int j = 0; j < 8; j++) acc[i][j] *= rs[i];

        #pragma unroll 4
        for (int k = 0; k < 64; k++) {
            float p[4];
            #pragma unroll
            for (int i = 0; i < 4; i++) p[i] = Ss[(tx * 4 + i) * 65 + k];
            float v[8];
            *(float4*)&v[0] = *(const float4*)(Vs + k * HD + ty * 8);
            *(float4*)&v[4] = *(const float4*)(Vs + k * HD + ty * 8 + 4);
            #pragma unroll
            for (int i = 0; i < 4; i++)
                #pragma unroll
                for (int j = 0; j < 8; j++)
                    acc[i][j] = fmaf(p[i], v[j], acc[i][j]);
        }
    }

    #pragma unroll
    for (int i = 0; i < 4; i++) {
        float inv = 1.0f / l_s[tx * 4 + i];
        float* orow = g_attn + (size_t)(q0 + tx * 4 + i) * HID + head * HD + ty * 8;
        *(float4*)(orow)     = make_float4(acc[i][0] * inv, acc[i][1] * inv,
                                           acc[i][2] * inv, acc[i][3] * inv);
        *(float4*)(orow + 4) = make_float4(acc[i][4] * inv, acc[i][5] * inv,
                                           acc[i][6] * inv, acc[i][7] * inv);
    }
}

// ---------------------------------------------------------------------------
extern "C" void kernel_launch(void* const* d_in, const int* in_sizes, int n_in,
                              void* d_out, int out_size)
{
    const float* hidden = (const float*)d_in[0];   // [4096, 2048]
    const float* w_qkv  = (const float*)d_in[1];   // [6144, 2048]
    const float* w_o    = (const float*)d_in[2];   // [2048, 2048]
    float* out = (float*)d_out;                    // [4096, 2048]

    float *qkv_ptr, *attn_ptr;
    cudaGetSymbolAddress((void**)&qkv_ptr, g_qkv);
    cudaGetSymbolAddress((void**)&attn_ptr, g_attn);
    __nv_bfloat16 *hid_h, *hid_l, *wq_h, *wq_l, *wo_h, *wo_l, *at_h, *at_l;
    cudaGetSymbolAddress((void**)&hid_h, g_hid_h);
    cudaGetSymbolAddress((void**)&hid_l, g_hid_l);
    cudaGetSymbolAddress((void**)&wq_h, g_wq_h);
    cudaGetSymbolAddress((void**)&wq_l, g_wq_l);
    cudaGetSymbolAddress((void**)&wo_h, g_wo_h);
    cudaGetSymbolAddress((void**)&wo_l, g_wo_l);
    cudaGetSymbolAddress((void**)&at_h, g_at_h);
    cudaGetSymbolAddress((void**)&at_l, g_at_l);

    const int gemm_smem = 2 * STAGE;   // 81920
    cudaFuncSetAttribute(gemm_bf16x3,
                         cudaFuncAttributeMaxDynamicSharedMemorySize, gemm_smem);

    // Split inputs into bf16 hi/lo planes
    split_kernel<<<(SEQ * HID / 4 + 255) / 256, 256>>>(hidden, hid_h, hid_l, SEQ * HID / 4);
    split_kernel<<<(QKVN * HID / 4 + 255) / 256, 256>>>(w_qkv, wq_h, wq_l, QKVN * HID / 4);
    split_kernel<<<(HID * HID / 4 + 255) / 256, 256>>>(w_o, wo_h, wo_l, HID * HID / 4);

    // 1) QKV projection (HMMA bf16x3)
    gemm_bf16x3<<<dim3(QKVN / 128, SEQ / 128), 256, gemm_smem>>>(
        hid_h, hid_l, wq_h, wq_l, qkv_ptr, SEQ, QKVN, HID);

    // 2) RoPE
    rope_kernel<<<SEQ, 256>>>();

    // 3) Causal flash attention (fp32 SIMT)
    size_t fsmem = (size_t)(128 * 64 + 64 * 128 * 2 + 64 * 65 + 3 * 64) * sizeof(float);
    cudaFuncSetAttribute(flash_kernel, cudaFuncAttributeMaxDynamicSharedMemorySize,
                         (int)fsmem);
    flash_kernel<<<dim3(SEQ / 64, NHEADS), 256, fsmem>>>();

    // 4) Split attention output, then O projection (HMMA bf16x3)
    split_kernel<<<(SEQ * HID / 4 + 255) / 256, 256>>>(attn_ptr, at_h, at_l, SEQ * HID / 4);
    gemm_bf16x3<<<dim3(HID / 128, SEQ / 128), 256, gemm_smem>>>(
        at_h, at_l, wo_h, wo_l, out, SEQ, HID, HID);
}

// round 4
// speedup vs baseline: 2.7653x; 1.6391x over previous
#include <cuda_runtime.h>
#include <cuda_bf16.h>
#include <math.h>
#include <cstdint>

#define SEQ   4096
#define HID   2048
#define NHEADS 16
#define HD    128
#define QKVN  6144   // (16 + 2*16) * 128

// Scratch (no cudaMalloc allowed)
__device__ float g_qkv[SEQ * QKVN];    // fp32 qkv after projection
__device__ float g_attn[SEQ * HID];    // fp32 attention output

// bf16 hi/lo planes for HMMA GEMMs
__device__ __nv_bfloat16 g_hid_h[SEQ * HID];
__device__ __nv_bfloat16 g_hid_l[SEQ * HID];
__device__ __nv_bfloat16 g_wq_h[QKVN * HID];
__device__ __nv_bfloat16 g_wq_l[QKVN * HID];
__device__ __nv_bfloat16 g_wo_h[HID * HID];
__device__ __nv_bfloat16 g_wo_l[HID * HID];
__device__ __nv_bfloat16 g_at_h[SEQ * HID];
__device__ __nv_bfloat16 g_at_l[SEQ * HID];

// ---------------------------------------------------------------------------
__device__ __forceinline__ uint32_t smem_u32(const void* p) {
    uint32_t a;
    asm("{ .reg .u64 t; cvta.to.shared.u64 t, %1; cvt.u32.u64 %0, t; }"
        : "=r"(a) : "l"(p));
    return a;
}

__device__ __forceinline__ void ldsm4(uint32_t* r, uint32_t addr) {
    asm volatile("ldmatrix.sync.aligned.m8n8.x4.shared.b16 {%0,%1,%2,%3}, [%4];"
                 : "=r"(r[0]), "=r"(r[1]), "=r"(r[2]), "=r"(r[3]) : "r"(addr));
}

__device__ __forceinline__ void ldsm4t(uint32_t* r, uint32_t addr) {
    asm volatile("ldmatrix.sync.aligned.m8n8.x4.trans.shared.b16 {%0,%1,%2,%3}, [%4];"
                 : "=r"(r[0]), "=r"(r[1]), "=r"(r[2]), "=r"(r[3]) : "r"(addr));
}

__device__ __forceinline__ void mma16816(float* c, const uint32_t* a, const uint32_t* b) {
    asm volatile(
        "mma.sync.aligned.m16n8k16.row.col.f32.bf16.bf16.f32 "
        "{%0,%1,%2,%3}, {%4,%5,%6,%7}, {%8,%9}, {%0,%1,%2,%3};"
        : "+f"(c[0]), "+f"(c[1]), "+f"(c[2]), "+f"(c[3])
        : "r"(a[0]), "r"(a[1]), "r"(a[2]), "r"(a[3]), "r"(b[0]), "r"(b[1]));
}

// split (x,y) fp32 -> bf16x2 hi + bf16x2 lo
__device__ __forceinline__ void pack_hilo(float x, float y, uint32_t& h, uint32_t& l) {
    __nv_bfloat162 hb = __float22bfloat162_rn(make_float2(x, y));
    float2 hf = __bfloat1622float2(hb);
    __nv_bfloat162 lb = __float22bfloat162_rn(make_float2(x - hf.x, y - hf.y));
    h = *(uint32_t*)&hb;
    l = *(uint32_t*)&lb;
}

// ---------------------------------------------------------------------------
// Split fp32 -> bf16 hi + bf16 lo planes (for GEMM operands)
// ---------------------------------------------------------------------------
__global__ void __launch_bounds__(256) split_kernel(
    const float* __restrict__ in, __nv_bfloat16* __restrict__ hi,
    __nv_bfloat16* __restrict__ lo, int n4)
{
    int i = blockIdx.x * 256 + threadIdx.x;
    if (i >= n4) return;
    float4 v = ((const float4*)in)[i];
    uint32_t h0, l0, h1, l1;
    pack_hilo(v.x, v.y, h0, l0);
    pack_hilo(v.z, v.w, h1, l1);
    ((uint2*)hi)[i] = make_uint2(h0, h1);
    ((uint2*)lo)[i] = make_uint2(l0, l1);
}

// ---------------------------------------------------------------------------
// bf16x3 HMMA GEMM NT (unchanged from round 3 — verified)
// ---------------------------------------------------------------------------
#define GPITCH 80
#define PLANE  (128 * GPITCH)
#define STAGE  (4 * PLANE)

__global__ void __launch_bounds__(256, 2)
gemm_bf16x3(const __nv_bfloat16* __restrict__ Ah, const __nv_bfloat16* __restrict__ Al,
            const __nv_bfloat16* __restrict__ Bh, const __nv_bfloat16* __restrict__ Bl,
            float* __restrict__ C, int M, int N, int K)
{
    extern __shared__ char smc[];
    uint32_t sbase = smem_u32(smc);

    const int tid  = threadIdx.x;
    const int lane = tid & 31;
    const int wid  = tid >> 5;
    const int m0 = blockIdx.y * 128;
    const int n0 = blockIdx.x * 128;
    const int wm = (wid & 3) * 32;
    const int wn = (wid >> 2) * 64;

    const __nv_bfloat16* gsrc0 = Ah + (size_t)m0 * K;
    const __nv_bfloat16* gsrc1 = Al + (size_t)m0 * K;
    const __nv_bfloat16* gsrc2 = Bh + (size_t)n0 * K;
    const __nv_bfloat16* gsrc3 = Bl + (size_t)n0 * K;

    const int lrow = tid >> 2;
    const int lkg  = tid & 3;

    auto load_stage = [&](int s, int k0) {
        const __nv_bfloat16* gs[4] = {gsrc0 + k0, gsrc1 + k0, gsrc2 + k0, gsrc3 + k0};
        #pragma unroll
        for (int p = 0; p < 4; p++) {
            uint32_t sp = sbase + s * STAGE + p * PLANE;
            #pragma unroll
            for (int half = 0; half < 2; half++) {
                int row = lrow + half * 64;
                uint32_t sa = sp + row * GPITCH + lkg * 16;
                const void* ga = gs[p] + (size_t)row * K + lkg * 8;
                asm volatile("cp.async.cg.shared.global [%0], [%1], 16;"
                             :: "r"(sa), "l"(ga));
            }
        }
        asm volatile("cp.async.commit_group;");
    };

    float acc[2][8][4];
    #pragma unroll
    for (int a = 0; a < 2; a++)
        #pragma unroll
        for (int b = 0; b < 8; b++)
            #pragma unroll
            for (int c = 0; c < 4; c++) acc[a][b][c] = 0.f;

    const int nk = K >> 5;
    load_stage(0, 0);

    const int grp = lane >> 3, r8 = lane & 7;
    const int arow_off = r8 + ((grp & 1) << 3);
    const int akk_off  = (grp >> 1) << 3;
    const int brow_off = r8 + ((grp >> 1) << 3);
    const int bkk_off  = (grp & 1) << 3;

    for (int kt = 0; kt < nk; kt++) {
        int cur = kt & 1;
        if (kt + 1 < nk) {
            load_stage(cur ^ 1, (kt + 1) << 5);
            asm volatile("cp.async.wait_group 1;");
        } else {
            asm volatile("cp.async.wait_group 0;");
        }
        __syncthreads();

        uint32_t stg = sbase + cur * STAGE;
        uint32_t sAh = stg, sAl = stg + PLANE, sBh = stg + 2 * PLANE, sBl = stg + 3 * PLANE;

        #pragma unroll
        for (int ks = 0; ks < 2; ks++) {
            int kb = ks * 16;
            uint32_t a_h[2][4], a_l[2][4];
            #pragma unroll
            for (int mt = 0; mt < 2; mt++) {
                uint32_t ad = (uint32_t)((wm + mt * 16 + arow_off) * GPITCH
                                         + (kb + akk_off) * 2);
                ldsm4(a_h[mt], sAh + ad);
                ldsm4(a_l[mt], sAl + ad);
            }
            #pragma unroll
            for (int np = 0; np < 4; np++) {
                uint32_t bh[4], bl[4];
                uint32_t bd = (uint32_t)((wn + np * 16 + brow_off) * GPITCH
                                         + (kb + bkk_off) * 2);
                ldsm4(bh, sBh + bd);
                ldsm4(bl, sBl + bd);
                #pragma unroll
                for (int mt = 0; mt < 2; mt++) {
                    mma16816(acc[mt][np * 2],     a_h[mt], &bh[0]);
                    mma16816(acc[mt][np * 2],     a_h[mt], &bl[0]);
                    mma16816(acc[mt][np * 2],     a_l[mt], &bh[0]);
                    mma16816(acc[mt][np * 2 + 1], a_h[mt], &bh[2]);
                    mma16816(acc[mt][np * 2 + 1], a_h[mt], &bl[2]);
                    mma16816(acc[mt][np * 2 + 1], a_l[mt], &bh[2]);
                }
            }
        }
        __syncthreads();
    }

    #pragma unroll
    for (int mt = 0; mt < 2; mt++) {
        int row0 = m0 + wm + mt * 16 + (lane >> 2);
        #pragma unroll
        for (int nt = 0; nt < 8; nt++) {
            int col = n0 + wn + nt * 8 + (lane & 3) * 2;
            *(float2*)(C + (size_t)row0 * N + col) =
                make_float2(acc[mt][nt][0], acc[mt][nt][1]);
            *(float2*)(C + (size_t)(row0 + 8) * N + col) =
                make_float2(acc[mt][nt][2], acc[mt][nt][3]);
        }
    }
}

// ---------------------------------------------------------------------------
// RoPE in-place on q, k of g_qkv
// ---------------------------------------------------------------------------
__global__ void __launch_bounds__(256) rope_kernel()
{
    int s = blockIdx.x;
    __shared__ float cs[64], sn[64];
    int t = threadIdx.x;
    if (t < 64) {
        float ex  = (float)(2 * t) / 128.0f;
        float inv = 1.0f / powf(10000.0f, ex);
        float f   = (float)s * inv;
        cs[t] = cosf(f);
        sn[t] = sinf(f);
    }
    __syncthreads();
    float* base = g_qkv + (size_t)s * QKVN;
    for (int p = t; p < 2 * NHEADS * 64; p += 256) {
        int h = p >> 6;
        int i = p & 63;
        float* x = base + h * HD;
        float xr = x[i], xi = x[i + 64];
        float c = cs[i], ss = sn[i];
        x[i]      = xr * c - xi * ss;
        x[i + 64] = xi * c + xr * ss;
    }
}

// ---------------------------------------------------------------------------
// HMMA flash attention (bf16x3, fp32 softmax/accum), causal.
// CTA = 128 queries x 1 head, 8 warps x 16 rows, 64-key tiles.
// Q scaled by 1/sqrt(128) before hi/lo split. V via ldmatrix.trans.
// ---------------------------------------------------------------------------
#define FP 272   // smem pitch bytes for 128 bf16 row (256B data + 16B pad)

__global__ void __launch_bounds__(256) flash_hmma()
{
    extern __shared__ char fsm[];
    char* pQh = fsm;
    char* pQl = fsm + 128 * FP;
    char* pKh = fsm + 2 * 128 * FP;
    char* pKl = pKh + 64 * FP;
    char* pVh = pKl + 64 * FP;
    char* pVl = pVh + 64 * FP;
    uint32_t sQh = smem_u32(pQh), sQl = smem_u32(pQl);
    uint32_t sKh = smem_u32(pKh), sKl = smem_u32(pKl);
    uint32_t sVh = smem_u32(pVh), sVl = smem_u32(pVl);

    const int tid  = threadIdx.x;
    const int lane = tid & 31;
    const int w    = tid >> 5;
    const int head = blockIdx.y;
    const int q0   = ((int)gridDim.x - 1 - (int)blockIdx.x) * 128;  // heavy first

    const float scale = 0.08838834764831845f;

    // Convert Q tile (scaled) -> hi/lo bf16 smem
    const float* Qg = g_qkv + (size_t)q0 * QKVN + head * HD;
    for (int idx = tid; idx < 128 * 32; idx += 256) {
        int r = idx >> 5, c4 = idx & 31;
        float4 v = *(const float4*)(Qg + (size_t)r * QKVN + c4 * 4);
        uint32_t h0, l0, h1, l1;
        pack_hilo(v.x * scale, v.y * scale, h0, l0);
        pack_hilo(v.z * scale, v.w * scale, h1, l1);
        int off = r * FP + c4 * 8;
        *(uint2*)(pQh + off) = make_uint2(h0, h1);
        *(uint2*)(pQl + off) = make_uint2(l0, l1);
    }

    const int grp = lane >> 3, r8 = lane & 7;
    const int arow = r8 + ((grp & 1) << 3);
    const int acol = (grp >> 1) << 3;       // halfs
    const int brow = r8 + ((grp >> 1) << 3);
    const int bcol = (grp & 1) << 3;

    float o[16][4];
    #pragma unroll
    for (int i = 0; i < 16; i++)
        #pragma unroll
        for (int j = 0; j < 4; j++) o[i][j] = 0.f;
    float m0 = -1e30f, m1 = -1e30f, l0 = 0.f, l1 = 0.f;

    const float* Kg = g_qkv + (size_t)(NHEADS + head) * HD;
    const float* Vg = g_qkv + (size_t)(2 * NHEADS + head) * HD;

    const int row0 = q0 + w * 16 + (lane >> 2);   // this thread's first row
    const int ntk = (q0 >> 6) + 2;

    for (int kt = 0; kt < ntk; kt++) {
        int k0 = kt << 6;
        __syncthreads();   // prior frag reads done before overwriting K/V
        for (int idx = tid; idx < 64 * 32; idx += 256) {
            int r = idx >> 5, c4 = idx & 31;
            const float* kp = Kg + (size_t)(k0 + r) * QKVN + c4 * 4;
            float4 kv = *(const float4*)kp;
            uint32_t h0_, l0_, h1_, l1_;
            pack_hilo(kv.x, kv.y, h0_, l0_);
            pack_hilo(kv.z, kv.w, h1_, l1_);
            int off = r * FP + c4 * 8;
            *(uint2*)(pKh + off) = make_uint2(h0_, h1_);
            *(uint2*)(pKl + off) = make_uint2(l0_, l1_);
            const float* vp = Vg + (size_t)(k0 + r) * QKVN + c4 * 4;
            float4 vv = *(const float4*)vp;
            pack_hilo(vv.x, vv.y, h0_, l0_);
            pack_hilo(vv.z, vv.w, h1_, l1_);
            *(uint2*)(pVh + off) = make_uint2(h0_, h1_);
            *(uint2*)(pVl + off) = make_uint2(l0_, l1_);
        }
        __syncthreads();

        if (k0 > q0 + w * 16 + 15) continue;   // warp fully masked

        // S = Q K^T  (16 x 64 per warp)
        float sc[8][4];
        #pragma unroll
        for (int i = 0; i < 8; i++)
            #pragma unroll
            for (int j = 0; j < 4; j++) sc[i][j] = 0.f;

        #pragma unroll
        for (int ks = 0; ks < 8; ks++) {
            uint32_t qh[4], ql[4];
            uint32_t qa = (uint32_t)((w * 16 + arow) * FP + (ks * 16 + acol) * 2);
            ldsm4(qh, sQh + qa);
            ldsm4(ql, sQl + qa);
            #pragma unroll
            for (int g = 0; g < 4; g++) {
                uint32_t kh[4], kl[4];
                uint32_t ka = (uint32_t)((g * 16 + brow) * FP + (ks * 16 + bcol) * 2);
                ldsm4(kh, sKh + ka);
                ldsm4(kl, sKl + ka);
                mma16816(sc[g * 2],     qh, &kh[0]);
                mma16816(sc[g * 2],     qh, &kl[0]);
                mma16816(sc[g * 2],     ql, &kh[0]);
                mma16816(sc[g * 2 + 1], qh, &kh[2]);
                mma16816(sc[g * 2 + 1], qh, &kl[2]);
                mma16816(sc[g * 2 + 1], ql, &kh[2]);
            }
        }

        // Causal mask
        if (k0 + 63 > row0) {
            #pragma unroll
            for (int nt = 0; nt < 8; nt++) {
                int colb = k0 + nt * 8 + (lane & 3) * 2;
                if (colb > row0)     sc[nt][0] = -1e30f;
                if (colb + 1 > row0) sc[nt][1] = -1e30f;
                if (colb > row0 + 8)     sc[nt][2] = -1e30f;
                if (colb + 1 > row0 + 8) sc[nt][3] = -1e30f;
            }
        }

        // Online softmax (registers; quad reduce)
        float mt0 = -1e30f, mt1 = -1e30f;
        #pragma unroll
        for (int nt = 0; nt < 8; nt++) {
            mt0 = fmaxf(mt0, fmaxf(sc[nt][0], sc[nt][1]));
            mt1 = fmaxf(mt1, fmaxf(sc[nt][2], sc[nt][3]));
        }
        mt0 = fmaxf(mt0, __shfl_xor_sync(0xffffffffu, mt0, 1));
        mt0 = fmaxf(mt0, __shfl_xor_sync(0xffffffffu, mt0, 2));
        mt1 = fmaxf(mt1, __shfl_xor_sync(0xffffffffu, mt1, 1));
        mt1 = fmaxf(mt1, __shfl_xor_sync(0xffffffffu, mt1, 2));
        float mn0 = fmaxf(m0, mt0), mn1 = fmaxf(m1, mt1);
        float f0 = __expf(m0 - mn0), f1 = __expf(m1 - mn1);
        m0 = mn0; m1 = mn1;

        float s0 = 0.f, s1 = 0.f;
        #pragma unroll
        for (int nt = 0; nt < 8; nt++) {
            sc[nt][0] = __expf(sc[nt][0] - mn0); s0 += sc[nt][0];
            sc[nt][1] = __expf(sc[nt][1] - mn0); s0 += sc[nt][1];
            sc[nt][2] = __expf(sc[nt][2] - mn1); s1 += sc[nt][2];
            sc[nt][3] = __expf(sc[nt][3] - mn1); s1 += sc[nt][3];
        }
        s0 += __shfl_xor_sync(0xffffffffu, s0, 1);
        s0 += __shfl_xor_sync(0xffffffffu, s0, 2);
        s1 += __shfl_xor_sync(0xffffffffu, s1, 1);
        s1 += __shfl_xor_sync(0xffffffffu, s1, 2);
        l0 = l0 * f0 + s0;
        l1 = l1 * f1 + s1;

        #pragma unroll
        for (int i = 0; i < 16; i++) {
            o[i][0] *= f0; o[i][1] *= f0;
            o[i][2] *= f1; o[i][3] *= f1;
        }

        // O += P V  (P from registers, V via ldmatrix.trans)
        #pragma unroll
        for (int ks = 0; ks < 4; ks++) {
            uint32_t ph[4], pl[4];
            int t0 = ks * 2, t1 = ks * 2 + 1;
            pack_hilo(sc[t0][0], sc[t0][1], ph[0], pl[0]);
            pack_hilo(sc[t0][2], sc[t0][3], ph[1], pl[1]);
            pack_hilo(sc[t1][0], sc[t1][1], ph[2], pl[2]);
            pack_hilo(sc[t1][2], sc[t1][3], ph[3], pl[3]);
            #pragma unroll
            for (int g = 0; g < 8; g++) {
                uint32_t vh[4], vl[4];
                uint32_t va = (uint32_t)((ks * 16 + arow) * FP + (g * 16 + acol) * 2);
                ldsm4t(vh, sVh + va);
                ldsm4t(vl, sVl + va);
                mma16816(o[g * 2],     ph, &vh[0]);
                mma16816(o[g * 2],     ph, &vl[0]);
                mma16816(o[g * 2],     pl, &vh[0]);
                mma16816(o[g * 2 + 1], ph, &vh[2]);
                mma16816(o[g * 2 + 1], ph, &vl[2]);
                mma16816(o[g * 2 + 1], pl, &vh[2]);
            }
        }
    }

    // Normalize + store
    float il0 = 1.0f / l0, il1 = 1.0f / l1;
    #pragma unroll
    for (int dt = 0; dt < 16; dt++) {
        int col = head * HD + dt * 8 + (lane & 3) * 2;
        *(float2*)(g_attn + (size_t)row0 * HID + col) =
            make_float2(o[dt][0] * il0, o[dt][1] * il0);
        *(float2*)(g_attn + (size_t)(row0 + 8) * HID + col) =
            make_float2(o[dt][2] * il1, o[dt][3] * il1);
    }
}

// ---------------------------------------------------------------------------
extern "C" void kernel_launch(void* const* d_in, const int* in_sizes, int n_in,
                              void* d_out, int out_size)
{
    const float* hidden = (const float*)d_in[0];
    const float* w_qkv  = (const float*)d_in[1];
    const float* w_o    = (const float*)d_in[2];
    float* out = (float*)d_out;

    float *qkv_ptr, *attn_ptr;
    cudaGetSymbolAddress((void**)&qkv_ptr, g_qkv);
    cudaGetSymbolAddress((void**)&attn_ptr, g_attn);
    __nv_bfloat16 *hid_h, *hid_l, *wq_h, *wq_l, *wo_h, *wo_l, *at_h, *at_l;
    cudaGetSymbolAddress((void**)&hid_h, g_hid_h);
    cudaGetSymbolAddress((void**)&hid_l, g_hid_l);
    cudaGetSymbolAddress((void**)&wq_h, g_wq_h);
    cudaGetSymbolAddress((void**)&wq_l, g_wq_l);
    cudaGetSymbolAddress((void**)&wo_h, g_wo_h);
    cudaGetSymbolAddress((void**)&wo_l, g_wo_l);
    cudaGetSymbolAddress((void**)&at_h, g_at_h);
    cudaGetSymbolAddress((void**)&at_l, g_at_l);

    const int gemm_smem = 2 * STAGE;
    cudaFuncSetAttribute(gemm_bf16x3,
                         cudaFuncAttributeMaxDynamicSharedMemorySize, gemm_smem);

    split_kernel<<<(SEQ * HID / 4 + 255) / 256, 256>>>(hidden, hid_h, hid_l, SEQ * HID / 4);
    split_kernel<<<(QKVN * HID / 4 + 255) / 256, 256>>>(w_qkv, wq_h, wq_l, QKVN * HID / 4);
    split_kernel<<<(HID * HID / 4 + 255) / 256, 256>>>(w_o, wo_h, wo_l, HID * HID / 4);

    // 1) QKV projection
    gemm_bf16x3<<<dim3(QKVN / 128, SEQ / 128), 256, gemm_smem>>>(
        hid_h, hid_l, wq_h, wq_l, qkv_ptr, SEQ, QKVN, HID);

    // 2) RoPE
    rope_kernel<<<SEQ, 256>>>();

    // 3) HMMA flash attention
    const int fl_smem = 2 * 128 * FP + 4 * 64 * FP;   // 139264
    cudaFuncSetAttribute(flash_hmma,
                         cudaFuncAttributeMaxDynamicSharedMemorySize, fl_smem);
    flash_hmma<<<dim3(SEQ / 128, NHEADS), 256, fl_smem>>>();

    // 4) O projection
    split_kernel<<<(SEQ * HID / 4 + 255) / 256, 256>>>(attn_ptr, at_h, at_l, SEQ * HID / 4);
    gemm_bf16x3<<<dim3(HID / 128, SEQ / 128), 256, gemm_smem>>>(
        at_h, at_l, wo_h, wo_l, out, SEQ, HID, HID);
}

// round 5
// speedup vs baseline: 3.1970x; 1.1561x over previous
#include <cuda_runtime.h>
#include <cuda_bf16.h>
#include <math.h>
#include <cstdint>

#define SEQ   4096
#define HID   2048
#define NHEADS 16
#define HD    128
#define QKVN  6144   // (16 + 2*16) * 128

// Scratch (no cudaMalloc allowed)
__device__ float g_qkv[SEQ * QKVN];    // fp32 qkv after projection

// bf16 hi/lo planes for HMMA GEMMs
__device__ __nv_bfloat16 g_hid_h[SEQ * HID];
__device__ __nv_bfloat16 g_hid_l[SEQ * HID];
__device__ __nv_bfloat16 g_wq_h[QKVN * HID];
__device__ __nv_bfloat16 g_wq_l[QKVN * HID];
__device__ __nv_bfloat16 g_wo_h[HID * HID];
__device__ __nv_bfloat16 g_wo_l[HID * HID];
__device__ __nv_bfloat16 g_at_h[SEQ * HID];
__device__ __nv_bfloat16 g_at_l[SEQ * HID];

// bf16 hi/lo planes for attention, [head][seq][128]
__device__ __nv_bfloat16 g_qh[NHEADS * SEQ * HD];
__device__ __nv_bfloat16 g_ql[NHEADS * SEQ * HD];
__device__ __nv_bfloat16 g_kh[NHEADS * SEQ * HD];
__device__ __nv_bfloat16 g_kl[NHEADS * SEQ * HD];
__device__ __nv_bfloat16 g_vh[NHEADS * SEQ * HD];
__device__ __nv_bfloat16 g_vl[NHEADS * SEQ * HD];

// ---------------------------------------------------------------------------
__device__ __forceinline__ uint32_t smem_u32(const void* p) {
    uint32_t a;
    asm("{ .reg .u64 t; cvta.to.shared.u64 t, %1; cvt.u32.u64 %0, t; }"
        : "=r"(a) : "l"(p));
    return a;
}

__device__ __forceinline__ void ldsm4(uint32_t* r, uint32_t addr) {
    asm volatile("ldmatrix.sync.aligned.m8n8.x4.shared.b16 {%0,%1,%2,%3}, [%4];"
                 : "=r"(r[0]), "=r"(r[1]), "=r"(r[2]), "=r"(r[3]) : "r"(addr));
}

__device__ __forceinline__ void ldsm4t(uint32_t* r, uint32_t addr) {
    asm volatile("ldmatrix.sync.aligned.m8n8.x4.trans.shared.b16 {%0,%1,%2,%3}, [%4];"
                 : "=r"(r[0]), "=r"(r[1]), "=r"(r[2]), "=r"(r[3]) : "r"(addr));
}

__device__ __forceinline__ void mma16816(float* c, const uint32_t* a, const uint32_t* b) {
    asm volatile(
        "mma.sync.aligned.m16n8k16.row.col.f32.bf16.bf16.f32 "
        "{%0,%1,%2,%3}, {%4,%5,%6,%7}, {%8,%9}, {%0,%1,%2,%3};"
        : "+f"(c[0]), "+f"(c[1]), "+f"(c[2]), "+f"(c[3])
        : "r"(a[0]), "r"(a[1]), "r"(a[2]), "r"(a[3]), "r"(b[0]), "r"(b[1]));
}

__device__ __forceinline__ void cpasync16(uint32_t sa, const void* ga) {
    asm volatile("cp.async.cg.shared.global [%0], [%1], 16;" :: "r"(sa), "l"(ga));
}

__device__ __forceinline__ void pack_hilo(float x, float y, uint32_t& h, uint32_t& l) {
    __nv_bfloat162 hb = __float22bfloat162_rn(make_float2(x, y));
    float2 hf = __bfloat1622float2(hb);
    __nv_bfloat162 lb = __float22bfloat162_rn(make_float2(x - hf.x, y - hf.y));
    h = *(uint32_t*)&hb;
    l = *(uint32_t*)&lb;
}

__device__ __forceinline__ void split1(float x, __nv_bfloat16& h, __nv_bfloat16& l) {
    h = __float2bfloat16(x);
    l = __float2bfloat16(x - __bfloat162float(h));
}

// ---------------------------------------------------------------------------
// Split fp32 -> bf16 hi + lo planes
// ---------------------------------------------------------------------------
__global__ void __launch_bounds__(256) split_kernel(
    const float* __restrict__ in, __nv_bfloat16* __restrict__ hi,
    __nv_bfloat16* __restrict__ lo, int n4)
{
    int i = blockIdx.x * 256 + threadIdx.x;
    if (i >= n4) return;
    float4 v = ((const float4*)in)[i];
    uint32_t h0, l0, h1, l1;
    pack_hilo(v.x, v.y, h0, l0);
    pack_hilo(v.z, v.w, h1, l1);
    ((uint2*)hi)[i] = make_uint2(h0, h1);
    ((uint2*)lo)[i] = make_uint2(l0, l1);
}

// ---------------------------------------------------------------------------
// bf16x3 HMMA GEMM NT (verified rounds 3-4)
// ---------------------------------------------------------------------------
#define GPITCH 80
#define PLANE  (128 * GPITCH)
#define STAGE  (4 * PLANE)

__global__ void __launch_bounds__(256, 2)
gemm_bf16x3(const __nv_bfloat16* __restrict__ Ah, const __nv_bfloat16* __restrict__ Al,
            const __nv_bfloat16* __restrict__ Bh, const __nv_bfloat16* __restrict__ Bl,
            float* __restrict__ C, int M, int N, int K)
{
    extern __shared__ char smc[];
    uint32_t sbase = smem_u32(smc);

    const int tid  = threadIdx.x;
    const int lane = tid & 31;
    const int wid  = tid >> 5;
    const int m0 = blockIdx.y * 128;
    const int n0 = blockIdx.x * 128;
    const int wm = (wid & 3) * 32;
    const int wn = (wid >> 2) * 64;

    const __nv_bfloat16* gsrc0 = Ah + (size_t)m0 * K;
    const __nv_bfloat16* gsrc1 = Al + (size_t)m0 * K;
    const __nv_bfloat16* gsrc2 = Bh + (size_t)n0 * K;
    const __nv_bfloat16* gsrc3 = Bl + (size_t)n0 * K;

    const int lrow = tid >> 2;
    const int lkg  = tid & 3;

    auto load_stage = [&](int s, int k0) {
        const __nv_bfloat16* gs[4] = {gsrc0 + k0, gsrc1 + k0, gsrc2 + k0, gsrc3 + k0};
        #pragma unroll
        for (int p = 0; p < 4; p++) {
            uint32_t sp = sbase + s * STAGE + p * PLANE;
            #pragma unroll
            for (int half = 0; half < 2; half++) {
                int row = lrow + half * 64;
                cpasync16(sp + row * GPITCH + lkg * 16,
                          gs[p] + (size_t)row * K + lkg * 8);
            }
        }
        asm volatile("cp.async.commit_group;");
    };

    float acc[2][8][4];
    #pragma unroll
    for (int a = 0; a < 2; a++)
        #pragma unroll
        for (int b = 0; b < 8; b++)
            #pragma unroll
            for (int c = 0; c < 4; c++) acc[a][b][c] = 0.f;

    const int nk = K >> 5;
    load_stage(0, 0);

    const int grp = lane >> 3, r8 = lane & 7;
    const int arow_off = r8 + ((grp & 1) << 3);
    const int akk_off  = (grp >> 1) << 3;
    const int brow_off = r8 + ((grp >> 1) << 3);
    const int bkk_off  = (grp & 1) << 3;

    for (int kt = 0; kt < nk; kt++) {
        int cur = kt & 1;
        if (kt + 1 < nk) {
            load_stage(cur ^ 1, (kt + 1) << 5);
            asm volatile("cp.async.wait_group 1;");
        } else {
            asm volatile("cp.async.wait_group 0;");
        }
        __syncthreads();

        uint32_t stg = sbase + cur * STAGE;
        uint32_t sAh = stg, sAl = stg + PLANE, sBh = stg + 2 * PLANE, sBl = stg + 3 * PLANE;

        #pragma unroll
        for (int ks = 0; ks < 2; ks++) {
            int kb = ks * 16;
            uint32_t a_h[2][4], a_l[2][4];
            #pragma unroll
            for (int mt = 0; mt < 2; mt++) {
                uint32_t ad = (uint32_t)((wm + mt * 16 + arow_off) * GPITCH
                                         + (kb + akk_off) * 2);
                ldsm4(a_h[mt], sAh + ad);
                ldsm4(a_l[mt], sAl + ad);
            }
            #pragma unroll
            for (int np = 0; np < 4; np++) {
                uint32_t bh[4], bl[4];
                uint32_t bd = (uint32_t)((wn + np * 16 + brow_off) * GPITCH
                                         + (kb + bkk_off) * 2);
                ldsm4(bh, sBh + bd);
                ldsm4(bl, sBl + bd);
                #pragma unroll
                for (int mt = 0; mt < 2; mt++) {
                    mma16816(acc[mt][np * 2],     a_h[mt], &bh[0]);
                    mma16816(acc[mt][np * 2],     a_h[mt], &bl[0]);
                    mma16816(acc[mt][np * 2],     a_l[mt], &bh[0]);
                    mma16816(acc[mt][np * 2 + 1], a_h[mt], &bh[2]);
                    mma16816(acc[mt][np * 2 + 1], a_h[mt], &bl[2]);
                    mma16816(acc[mt][np * 2 + 1], a_l[mt], &bh[2]);
                }
            }
        }
        __syncthreads();
    }

    #pragma unroll
    for (int mt = 0; mt < 2; mt++) {
        int row0 = m0 + wm + mt * 16 + (lane >> 2);
        #pragma unroll
        for (int nt = 0; nt < 8; nt++) {
            int col = n0 + wn + nt * 8 + (lane & 3) * 2;
            *(float2*)(C + (size_t)row0 * N + col) =
                make_float2(acc[mt][nt][0], acc[mt][nt][1]);
            *(float2*)(C + (size_t)(row0 + 8) * N + col) =
                make_float2(acc[mt][nt][2], acc[mt][nt][3]);
        }
    }
}

// ---------------------------------------------------------------------------
// RoPE + split: q (scaled), k, v of g_qkv -> bf16 hi/lo planes [head][seq][128]
// ---------------------------------------------------------------------------
__global__ void __launch_bounds__(256) rope_split_kernel()
{
    int s = blockIdx.x;
    __shared__ float cs[64], sn[64];
    int t = threadIdx.x;
    if (t < 64) {
        float ex  = (float)(2 * t) / 128.0f;
        float inv = 1.0f / powf(10000.0f, ex);
        float f   = (float)s * inv;
        cs[t] = cosf(f);
        sn[t] = sinf(f);
    }
    __syncthreads();
    const float scale = 0.08838834764831845f;
    const float* base = g_qkv + (size_t)s * QKVN;

    // q and k: 2 sections x 16 heads x 64 pairs
    for (int p = t; p < 2048; p += 256) {
        int sec = p >> 10;          // 0 = q, 1 = k
        int h   = (p >> 6) & 15;
        int i   = p & 63;
        const float* x = base + (sec * NHEADS + h) * HD;
        float xr = x[i], xi = x[i + 64];
        float c = cs[i], ss = sn[i];
        float yr = xr * c - xi * ss;
        float yi = xi * c + xr * ss;
        if (sec == 0) { yr *= scale; yi *= scale; }
        __nv_bfloat16 hr, lr, hi_, li_;
        split1(yr, hr, lr);
        split1(yi, hi_, li_);
        size_t o = (size_t)h * SEQ * HD + (size_t)s * HD + i;
        if (sec == 0) {
            g_qh[o] = hr; g_ql[o] = lr;
            g_qh[o + 64] = hi_; g_ql[o + 64] = li_;
        } else {
            g_kh[o] = hr; g_kl[o] = lr;
            g_kh[o + 64] = hi_; g_kl[o + 64] = li_;
        }
    }
    // v: 16 heads x 128
    for (int p = t; p < NHEADS * HD; p += 256) {
        int h = p >> 7, d = p & 127;
        float v = base[(2 * NHEADS + h) * HD + d];
        __nv_bfloat16 hv, lv;
        split1(v, hv, lv);
        size_t o = (size_t)h * SEQ * HD + (size_t)s * HD + d;
        g_vh[o] = hv; g_vl[o] = lv;
    }
}

// ---------------------------------------------------------------------------
// HMMA flash attention v2: pre-split bf16 inputs, cp.async double-buffered K/V,
// XOR-swizzled smem, bf16 hi/lo output planes. CTA = 128 q x 1 head, 8 warps.
// ---------------------------------------------------------------------------
#define FSW(row, c16) (((row) << 8) + ((((c16) ^ ((row) & 7))) << 4))
#define KVPL 16384             // bytes per KV plane (64 rows x 256B)
#define KVST 65536             // bytes per KV stage (4 planes)

__global__ void __launch_bounds__(256) flash_hmma()
{
    extern __shared__ char fsm[];
    uint32_t sQh = smem_u32(fsm);
    uint32_t sQl = sQh + 32768;
    uint32_t sKV = sQh + 65536;

    const int tid  = threadIdx.x;
    const int lane = tid & 31;
    const int w    = tid >> 5;
    const int head = blockIdx.y;
    const int q0   = ((int)gridDim.x - 1 - (int)blockIdx.x) * 128;  // heavy first

    const size_t hoff = (size_t)head * SEQ * HD;
    const __nv_bfloat16* Qh = g_qh + hoff;
    const __nv_bfloat16* Ql = g_ql + hoff;
    const __nv_bfloat16* Kh = g_kh + hoff;
    const __nv_bfloat16* Kl = g_kl + hoff;
    const __nv_bfloat16* Vh = g_vh + hoff;
    const __nv_bfloat16* Vl = g_vl + hoff;

    // Q tile loads (2 planes x 128 rows x 16 chunks)
    #pragma unroll
    for (int i = 0; i < 8; i++) {
        int idx = tid + i * 256;
        int r = idx >> 4, c16 = idx & 15;
        uint32_t o = FSW(r, c16);
        const __nv_bfloat16* g = Qh + (size_t)(q0 + r) * HD + c16 * 8;
        cpasync16(sQh + o, g);
        cpasync16(sQl + o, Ql + (size_t)(q0 + r) * HD + c16 * 8);
    }

    auto load_kv = [&](int kt) {
        int k0 = kt << 6;
        uint32_t st = sKV + (kt & 1) * KVST;
        #pragma unroll
        for (int i = 0; i < 4; i++) {
            int idx = tid + i * 256;
            int r = idx >> 4, c16 = idx & 15;
            uint32_t o = FSW(r, c16);
            size_t go = (size_t)(k0 + r) * HD + c16 * 8;
            cpasync16(st + o,            Kh + go);
            cpasync16(st + KVPL + o,     Kl + go);
            cpasync16(st + 2 * KVPL + o, Vh + go);
            cpasync16(st + 3 * KVPL + o, Vl + go);
        }
        asm volatile("cp.async.commit_group;");
    };

    const int ntk = (q0 >> 6) + 2;
    load_kv(0);   // group includes Q loads

    const int grp = lane >> 3, r8 = lane & 7;
    const int arow = r8 + ((grp & 1) << 3);
    const int ac16 = grp >> 1;     // 0/1: 16B half within 32B k-step
    const int brow = r8 + ((grp >> 1) << 3);
    const int bc16 = grp & 1;

    float o[16][4];
    #pragma unroll
    for (int i = 0; i < 16; i++)
        #pragma unroll
        for (int j = 0; j < 4; j++) o[i][j] = 0.f;
    float m0 = -1e30f, m1 = -1e30f, l0 = 0.f, l1 = 0.f;

    const int row0 = q0 + w * 16 + (lane >> 2);
    const int wlast = q0 + w * 16 + 15;

    for (int kt = 0; kt < ntk; kt++) {
        int k0 = kt << 6;
        int cur = kt & 1;
        if (kt + 1 < ntk) {
            load_kv(kt + 1);
            asm volatile("cp.async.wait_group 1;");
        } else {
            asm volatile("cp.async.wait_group 0;");
        }
        __syncthreads();

        if (k0 <= wlast) {
            uint32_t st = sKV + cur * KVST;
            uint32_t sKh = st, sKl = st + KVPL, sVh = st + 2 * KVPL, sVl = st + 3 * KVPL;

            // S = Q K^T (16 x 64 per warp)
            float sc[8][4];
            #pragma unroll
            for (int i = 0; i < 8; i++)
                #pragma unroll
                for (int j = 0; j < 4; j++) sc[i][j] = 0.f;

            #pragma unroll
            for (int ks = 0; ks < 8; ks++) {
                uint32_t qh[4], ql[4];
                int qr = w * 16 + arow, qc = ks * 2 + ac16;
                ldsm4(qh, sQh + FSW(qr, qc));
                ldsm4(ql, sQl + FSW(qr, qc));
                #pragma unroll
                for (int g = 0; g < 4; g++) {
                    uint32_t kh[4], kl[4];
                    int kr = g * 16 + brow, kc = ks * 2 + bc16;
                    ldsm4(kh, sKh + FSW(kr, kc));
                    ldsm4(kl, sKl + FSW(kr, kc));
                    mma16816(sc[g * 2],     qh, &kh[0]);
                    mma16816(sc[g * 2],     qh, &kl[0]);
                    mma16816(sc[g * 2],     ql, &kh[0]);
                    mma16816(sc[g * 2 + 1], qh, &kh[2]);
                    mma16816(sc[g * 2 + 1], qh, &kl[2]);
                    mma16816(sc[g * 2 + 1], ql, &kh[2]);
                }
            }

            // Causal mask
            if (k0 + 63 > row0) {
                #pragma unroll
                for (int nt = 0; nt < 8; nt++) {
                    int colb = k0 + nt * 8 + (lane & 3) * 2;
                    if (colb > row0)     sc[nt][0] = -1e30f;
                    if (colb + 1 > row0) sc[nt][1] = -1e30f;
                    if (colb > row0 + 8)     sc[nt][2] = -1e30f;
                    if (colb + 1 > row0 + 8) sc[nt][3] = -1e30f;
                }
            }

            // Online softmax
            float mt0 = -1e30f, mt1 = -1e30f;
            #pragma unroll
            for (int nt = 0; nt < 8; nt++) {
                mt0 = fmaxf(mt0, fmaxf(sc[nt][0], sc[nt][1]));
                mt1 = fmaxf(mt1, fmaxf(sc[nt][2], sc[nt][3]));
            }
            mt0 = fmaxf(mt0, __shfl_xor_sync(0xffffffffu, mt0, 1));
            mt0 = fmaxf(mt0, __shfl_xor_sync(0xffffffffu, mt0, 2));
            mt1 = fmaxf(mt1, __shfl_xor_sync(0xffffffffu, mt1, 1));
            mt1 = fmaxf(mt1, __shfl_xor_sync(0xffffffffu, mt1, 2));
            float mn0 = fmaxf(m0, mt0), mn1 = fmaxf(m1, mt1);
            float f0 = __expf(m0 - mn0), f1 = __expf(m1 - mn1);
            m0 = mn0; m1 = mn1;

            float s0 = 0.f, s1 = 0.f;
            #pragma unroll
            for (int nt = 0; nt < 8; nt++) {
                sc[nt][0] = __expf(sc[nt][0] - mn0); s0 += sc[nt][0];
                sc[nt][1] = __expf(sc[nt][1] - mn0); s0 += sc[nt][1];
                sc[nt][2] = __expf(sc[nt][2] - mn1); s1 += sc[nt][2];
                sc[nt][3] = __expf(sc[nt][3] - mn1); s1 += sc[nt][3];
            }
            s0 += __shfl_xor_sync(0xffffffffu, s0, 1);
            s0 += __shfl_xor_sync(0xffffffffu, s0, 2);
            s1 += __shfl_xor_sync(0xffffffffu, s1, 1);
            s1 += __shfl_xor_sync(0xffffffffu, s1, 2);
            l0 = l0 * f0 + s0;
            l1 = l1 * f1 + s1;

            #pragma unroll
            for (int i = 0; i < 16; i++) {
                o[i][0] *= f0; o[i][1] *= f0;
                o[i][2] *= f1; o[i][3] *= f1;
            }

            // O += P V
            #pragma unroll
            for (int ks = 0; ks < 4; ks++) {
                uint32_t ph[4], pl[4];
                int t0 = ks * 2, t1 = ks * 2 + 1;
                pack_hilo(sc[t0][0], sc[t0][1], ph[0], pl[0]);
                pack_hilo(sc[t0][2], sc[t0][3], ph[1], pl[1]);
                pack_hilo(sc[t1][0], sc[t1][1], ph[2], pl[2]);
                pack_hilo(sc[t1][2], sc[t1][3], ph[3], pl[3]);
                #pragma unroll
                for (int g = 0; g < 8; g++) {
                    uint32_t vh[4], vl[4];
                    int vr = ks * 16 + arow, vc = g * 2 + ac16;
                    ldsm4t(vh, sVh + FSW(vr, vc));
                    ldsm4t(vl, sVl + FSW(vr, vc));
                    mma16816(o[g * 2],     ph, &vh[0]);
                    mma16816(o[g * 2],     ph, &vl[0]);
                    mma16816(o[g * 2],     pl, &vh[0]);
                    mma16816(o[g * 2 + 1], ph, &vh[2]);
                    mma16816(o[g * 2 + 1], ph, &vl[2]);
                    mma16816(o[g * 2 + 1], pl, &vh[2]);
                }
            }
        }
        __syncthreads();
    }

    // Normalize + store as bf16 hi/lo planes (O-proj A operand)
    float il0 = 1.0f / l0, il1 = 1.0f / l1;
    #pragma unroll
    for (int dt = 0; dt < 16; dt++) {
        int col = head * HD + dt * 8 + (lane & 3) * 2;
        uint32_t h, l;
        pack_hilo(o[dt][0] * il0, o[dt][1] * il0, h, l);
        *(uint32_t*)(g_at_h + (size_t)row0 * HID + col) = h;
        *(uint32_t*)(g_at_l + (size_t)row0 * HID + col) = l;
        pack_hilo(o[dt][2] * il1, o[dt][3] * il1, h, l);
        *(uint32_t*)(g_at_h + (size_t)(row0 + 8) * HID + col) = h;
        *(uint32_t*)(g_at_l + (size_t)(row0 + 8) * HID + col) = l;
    }
}

// ---------------------------------------------------------------------------
extern "C" void kernel_launch(void* const* d_in, const int* in_sizes, int n_in,
                              void* d_out, int out_size)
{
    const float* hidden = (const float*)d_in[0];
    const float* w_qkv  = (const float*)d_in[1];
    const float* w_o    = (const float*)d_in[2];
    float* out = (float*)d_out;

    float* qkv_ptr;
    cudaGetSymbolAddress((void**)&qkv_ptr, g_qkv);
    __nv_bfloat16 *hid_h, *hid_l, *wq_h, *wq_l, *wo_h, *wo_l, *at_h, *at_l;
    cudaGetSymbolAddress((void**)&hid_h, g_hid_h);
    cudaGetSymbolAddress((void**)&hid_l, g_hid_l);
    cudaGetSymbolAddress((void**)&wq_h, g_wq_h);
    cudaGetSymbolAddress((void**)&wq_l, g_wq_l);
    cudaGetSymbolAddress((void**)&wo_h, g_wo_h);
    cudaGetSymbolAddress((void**)&wo_l, g_wo_l);
    cudaGetSymbolAddress((void**)&at_h, g_at_h);
    cudaGetSymbolAddress((void**)&at_l, g_at_l);

    const int gemm_smem = 2 * STAGE;
    cudaFuncSetAttribute(gemm_bf16x3,
                         cudaFuncAttributeMaxDynamicSharedMemorySize, gemm_smem);

    split_kernel<<<(SEQ * HID / 4 + 255) / 256, 256>>>(hidden, hid_h, hid_l, SEQ * HID / 4);
    split_kernel<<<(QKVN * HID / 4 + 255) / 256, 256>>>(w_qkv, wq_h, wq_l, QKVN * HID / 4);
    split_kernel<<<(HID * HID / 4 + 255) / 256, 256>>>(w_o, wo_h, wo_l, HID * HID / 4);

    // 1) QKV projection
    gemm_bf16x3<<<dim3(QKVN / 128, SEQ / 128), 256, gemm_smem>>>(
        hid_h, hid_l, wq_h, wq_l, qkv_ptr, SEQ, QKVN, HID);

    // 2) RoPE + split to bf16 planes
    rope_split_kernel<<<SEQ, 256>>>();

    // 3) HMMA flash attention (cp.async double-buffered)
    const int fl_smem = 65536 + 2 * KVST;   // 196608
    cudaFuncSetAttribute(flash_hmma,
                         cudaFuncAttributeMaxDynamicSharedMemorySize, fl_smem);
    flash_hmma<<<dim3(SEQ / 128, NHEADS), 256, fl_smem>>>();

    // 4) O projection (reads bf16 planes written by flash)
    gemm_bf16x3<<<dim3(HID / 128, SEQ / 128), 256, gemm_smem>>>(
        at_h, at_l, wo_h, wo_l, out, SEQ, HID, HID);
}